// round 4
// baseline (speedup 1.0000x reference)
#include <cuda_runtime.h>
#include <cuda_bf16.h>

// SmoothLDDTLoss — b=2, n=4096. Single fused kernel.
// Upper-triangle tiling, IR=2 rows/thread, f32x2-packed over j (2 cols/lane).
// Nearest-node smem LUT (2048 bins) for the 4-sigmoid sum, magic-FFMA index.

#define NTOK 4096
#define TJ 128
#define TI 256
#define NTILES_B 272              // sum_{I=0}^{15} (32 - 2I)
#define TOTAL_CTAS (2 * NTILES_B)

#define TBL_N 2048
#define TBL_H 0.0078125f          // 16 / 2048
#define DD_CLAMP 15.9921875f      // 2047 / 128

typedef unsigned long long ull;

__device__ double g_acc[4];       // [num0, den0, num1, den1]
__device__ int g_done;

__device__ __forceinline__ float fsqrt_approx(float x) {
    float r; asm("sqrt.approx.f32 %0, %1;" : "=f"(r) : "f"(x)); return r;
}
__device__ __forceinline__ ull pack2(float a, float b) {
    ull r; asm("mov.b64 %0, {%1, %2};" : "=l"(r) : "f"(a), "f"(b)); return r;
}
__device__ __forceinline__ void unpack2(ull v, float& a, float& b) {
    asm("mov.b64 {%0, %1}, %2;" : "=f"(a), "=f"(b) : "l"(v));
}
__device__ __forceinline__ ull add2(ull a, ull b) {
    ull r; asm("add.rn.f32x2 %0, %1, %2;" : "=l"(r) : "l"(a), "l"(b)); return r;
}
__device__ __forceinline__ ull mul2(ull a, ull b) {
    ull r; asm("mul.rn.f32x2 %0, %1, %2;" : "=l"(r) : "l"(a), "l"(b)); return r;
}
__device__ __forceinline__ ull fma2(ull a, ull b, ull c) {
    ull r; asm("fma.rn.f32x2 %0, %1, %2, %3;" : "=l"(r) : "l"(a), "l"(b), "l"(c)); return r;
}

// sum of 4 sigmoids sigma(t - x), t in {0.5,1,2,4}; rational form: 1 exp + 1 div
__device__ __forceinline__ float sig4c(float x) {
    const float C0 = 0.60653066f, C1 = 0.36787944f, C2 = 0.13533528f, C3 = 0.018315639f;
    float e = __expf(x);
    float b0 = fmaf(e, C0, 1.0f), b1 = fmaf(e, C1, 1.0f);
    float b2 = fmaf(e, C2, 1.0f), b3 = fmaf(e, C3, 1.0f);
    float p01 = b0 * b1, p23 = b2 * b3;
    float numr = fmaf(b0 + b1, p23, (b2 + b3) * p01);
    return __fdividef(numr, p01 * p23);
}

__device__ __forceinline__ float lut_v(float dd, const float* __restrict__ tbl) {
    int ib = __float_as_int(fmaf(dd, 512.0f, 8388608.0f)) & 0x1FFC;
    return *(const float*)((const char*)tbl + ib);
}

struct Row {
    ull npx, npy, npz, ntx, nty, ntz;   // broadcast-packed NEGATED i coords
    float nuc675;                        // 675 if nucleotide else 0
};

__device__ __forceinline__ void row_step(
    const Row& r, ull jx, ull jy, ull jz, ull tx, ull ty, ull tz,
    float wp0, float wp1, float wt0, float wt1,
    const float* __restrict__ tbl, float& num, float& den)
{
    ull dx = add2(jx, r.npx), dy = add2(jy, r.npy), dz = add2(jz, r.npz);
    ull d2p = mul2(dx, dx); d2p = fma2(dy, dy, d2p); d2p = fma2(dz, dz, d2p);
    ull ex = add2(tx, r.ntx), ey = add2(ty, r.nty), ez = add2(tz, r.ntz);
    ull d2t = mul2(ex, ex); d2t = fma2(ey, ey, d2t); d2t = fma2(ez, ez, d2t);

    float d2p0, d2p1, d2t0, d2t1;
    unpack2(d2p, d2p0, d2p1);
    unpack2(d2t, d2t0, d2t1);

    float cut0 = fmaf(wp0, r.nuc675, 225.0f);
    float cut1 = fmaf(wp1, r.nuc675, 225.0f);
    float m0 = (d2t0 < cut0) ? wt0 : 0.0f;
    float m1 = (d2t1 < cut1) ? wt1 : 0.0f;

    float dd0 = fminf(fabsf(fsqrt_approx(d2t0) - fsqrt_approx(d2p0)), DD_CLAMP);
    float dd1 = fminf(fabsf(fsqrt_approx(d2t1) - fsqrt_approx(d2p1)), DD_CLAMP);
    float v0 = lut_v(dd0, tbl);
    float v1 = lut_v(dd1, tbl);

    num = fmaf(v0, m0, num);
    den += m0;
    num = fmaf(v1, m1, num);
    den += m1;
}

// scalar path for diagonal-edge tiles
__device__ __forceinline__ void accum_scalar(
    float px, float py, float pz, float tx, float ty, float tz, float nuc675,
    float jx, float jy, float jz, float jtx, float jty, float jtz,
    float wp, float wt, const float* __restrict__ tbl,
    float& num, float& den, bool active)
{
    float dx = px - jx, dy = py - jy, dz = pz - jz;
    float d2p = fmaf(dx, dx, fmaf(dy, dy, dz * dz));
    float ex = tx - jtx, ey = ty - jty, ez = tz - jtz;
    float d2t = fmaf(ex, ex, fmaf(ey, ey, ez * ez));
    float cut2 = fmaf(wp, nuc675, 225.0f);
    float m = (d2t < cut2 && active) ? wt : 0.0f;
    float dd = fminf(fabsf(fsqrt_approx(d2t) - fsqrt_approx(d2p)), DD_CLAMP);
    float v = lut_v(dd, tbl);
    num = fmaf(v, m, num);
    den += m;
}

__global__ void __launch_bounds__(128)
lddt_fused(const float* __restrict__ pred,
           const float* __restrict__ truec,
           const int* __restrict__ is_dna,
           const int* __restrict__ is_rna,
           const int* __restrict__ cmask,
           float* __restrict__ out)
{
    int lin = blockIdx.x;
    const int b = (lin >= NTILES_B) ? 1 : 0;
    lin -= b * NTILES_B;
    int I = 0;
    {
        int cnt = 32;
        while (lin >= cnt) { lin -= cnt; I++; cnt -= 2; }
    }
    const int J = 2 * I + lin;

    const int tid = threadIdx.x;

    __shared__ float tbl[TBL_N];
    // packed j-tile: per 2-j group g: {x2,y2}, {z2,tx2}, {ty2,tz2}, {wp2,wt2}
    __shared__ ulonglong2 sA[TJ / 2], sB[TJ / 2], sC[TJ / 2], sD[TJ / 2];

    for (int k = tid; k < TBL_N; k += 128)
        tbl[k] = sig4c(((float)k + 0.5f) * TBL_H);

    const int base = b * NTOK;

    {
        const int jg = base + J * TJ + tid;
        float px = pred[3 * jg + 0], py = pred[3 * jg + 1], pz = pred[3 * jg + 2];
        float tx = truec[3 * jg + 0], ty = truec[3 * jg + 1], tz = truec[3 * jg + 2];
        float wp = (is_dna[jg] != 0 || is_rna[jg] != 0) ? 1.0f : 0.0f;
        float wt = (cmask[jg] != 0) ? 1.0f : 0.0f;
        const int g = tid >> 1, h = tid & 1;
        ((float*)&sA[g])[h]     = px;  ((float*)&sA[g])[2 + h] = py;
        ((float*)&sB[g])[h]     = pz;  ((float*)&sB[g])[2 + h] = tx;
        ((float*)&sC[g])[h]     = ty;  ((float*)&sC[g])[2 + h] = tz;
        ((float*)&sD[g])[h]     = wp;  ((float*)&sD[g])[2 + h] = wt;
    }

    const int ig0 = base + I * TI + tid;
    const int ig1 = ig0 + 128;
    Row r0, r1;
    float p0x = pred[3 * ig0 + 0], p0y = pred[3 * ig0 + 1], p0z = pred[3 * ig0 + 2];
    float t0x = truec[3 * ig0 + 0], t0y = truec[3 * ig0 + 1], t0z = truec[3 * ig0 + 2];
    float p1x = pred[3 * ig1 + 0], p1y = pred[3 * ig1 + 1], p1z = pred[3 * ig1 + 2];
    float t1x = truec[3 * ig1 + 0], t1y = truec[3 * ig1 + 1], t1z = truec[3 * ig1 + 2];
    r0.npx = pack2(-p0x, -p0x); r0.npy = pack2(-p0y, -p0y); r0.npz = pack2(-p0z, -p0z);
    r0.ntx = pack2(-t0x, -t0x); r0.nty = pack2(-t0y, -t0y); r0.ntz = pack2(-t0z, -t0z);
    r1.npx = pack2(-p1x, -p1x); r1.npy = pack2(-p1y, -p1y); r1.npz = pack2(-p1z, -p1z);
    r1.ntx = pack2(-t1x, -t1x); r1.nty = pack2(-t1y, -t1y); r1.ntz = pack2(-t1z, -t1z);
    r0.nuc675 = (is_dna[ig0] != 0 || is_rna[ig0] != 0) ? 675.0f : 0.0f;
    r1.nuc675 = (is_dna[ig1] != 0 || is_rna[ig1] != 0) ? 675.0f : 0.0f;
    const float cm0 = (cmask[ig0] != 0) ? 1.0f : 0.0f;
    const float cm1 = (cmask[ig1] != 0) ? 1.0f : 0.0f;

    __syncthreads();

    float n0 = 0.0f, d0 = 0.0f, n1 = 0.0f, d1 = 0.0f;

    if (J >= 2 * I + 2) {
        // hot path: packed, branch-free
        #pragma unroll 4
        for (int g = 0; g < TJ / 2; ++g) {
            ulonglong2 A = sA[g], B = sB[g], C = sC[g], D = sD[g];
            float wp0, wp1, wt0, wt1;
            unpack2(D.x, wp0, wp1);
            unpack2(D.y, wt0, wt1);
            row_step(r0, A.x, A.y, B.x, B.y, C.x, C.y, wp0, wp1, wt0, wt1, tbl, n0, d0);
            row_step(r1, A.x, A.y, B.x, B.y, C.x, C.y, wp0, wp1, wt0, wt1, tbl, n1, d1);
        }
    } else {
        // edge tiles: scalar with per-lane bounds
        const bool diag = (J == 2 * I);       // row0 j>tid, row1 none
        const int j0 = diag ? (tid + 1) : 0;  // J==2I+1: row0 full, row1 j>tid
        for (int j = j0; j < TJ; ++j) {
            const float* a = (const float*)&sA[j >> 1];
            const float* bb = (const float*)&sB[j >> 1];
            const float* c = (const float*)&sC[j >> 1];
            const float* d = (const float*)&sD[j >> 1];
            int h = j & 1;
            float jx = a[h], jy = a[2 + h], jz = bb[h];
            float jtx = bb[2 + h], jty = c[h], jtz = c[2 + h];
            float wp = d[h], wt = d[2 + h];
            accum_scalar(p0x, p0y, p0z, t0x, t0y, t0z, r0.nuc675,
                         jx, jy, jz, jtx, jty, jtz, wp, wt, tbl, n0, d0, true);
            if (!diag)
                accum_scalar(p1x, p1y, p1z, t1x, t1y, t1z, r1.nuc675,
                             jx, jy, jz, jtx, jty, jtz, wp, wt, tbl, n1, d1, j > tid);
        }
    }

    float acc_num = fmaf(n0, cm0, n1 * cm1);
    float acc_den = fmaf(d0, cm0, d1 * cm1);

    #pragma unroll
    for (int o = 16; o > 0; o >>= 1) {
        acc_num += __shfl_xor_sync(0xFFFFFFFFu, acc_num, o);
        acc_den += __shfl_xor_sync(0xFFFFFFFFu, acc_den, o);
    }
    __shared__ float rn[4], rd[4];
    const int wid = tid >> 5;
    if ((tid & 31) == 0) { rn[wid] = acc_num; rd[wid] = acc_den; }
    __syncthreads();

    if (tid == 0) {
        float tn = rn[0] + rn[1] + rn[2] + rn[3];
        float td = rd[0] + rd[1] + rd[2] + rd[3];
        atomicAdd(&g_acc[2 * b + 0], (double)tn);
        atomicAdd(&g_acc[2 * b + 1], (double)td);
        __threadfence();
        int done = atomicAdd(&g_done, 1);
        if (done == TOTAL_CTAS - 1) {
            volatile double* acc = g_acc;
            double num0 = acc[0], den0 = acc[1], num1 = acc[2], den1 = acc[3];
            double e0 = 2.0 * den0; if (e0 < 1.0) e0 = 1.0;
            double e1 = 2.0 * den1; if (e1 < 1.0) e1 = 1.0;
            double l0 = (0.5 * num0) / e0;
            double l1 = (0.5 * num1) / e1;
            out[0] = (float)(1.0 - 0.5 * (l0 + l1));
            acc[0] = 0.0; acc[1] = 0.0; acc[2] = 0.0; acc[3] = 0.0;
            g_done = 0;
            __threadfence();
        }
    }
}

extern "C" void kernel_launch(void* const* d_in, const int* in_sizes, int n_in,
                              void* d_out, int out_size) {
    const float* pred  = (const float*)d_in[0];
    const float* truec = (const float*)d_in[1];
    const int*   dna   = (const int*)d_in[2];
    const int*   rna   = (const int*)d_in[3];
    const int*   cm    = (const int*)d_in[4];

    lddt_fused<<<TOTAL_CTAS, 128>>>(pred, truec, dna, rna, cm, (float*)d_out);
}

// round 5
// speedup vs baseline: 1.1385x; 1.1385x over previous
#include <cuda_runtime.h>
#include <cuda_bf16.h>

// SmoothLDDTLoss — b=2, n=4096. Single fused kernel.
// Upper-triangle, 256x64 tiles (IR=2 rows/thread), 1088 CTAs for occupancy.
// Interpolated smem LUT (1024 bins) for the 4-sigmoid sum; cheap 2-pass fill.

#define NTOK 4096
#define TJ 64
#define TI 256
#define NTILES_B 544              // sum_{I=0}^{15} (64 - 4I)
#define TOTAL_CTAS (2 * NTILES_B)

#define TBL_N 1024
#define TBL_H 0.015625f           // 16 / 1024
#define TBL_SCALE 64.0f
#define DD_CLAMP 15.984375f       // 1023 * H

__device__ double g_acc[4];       // [num0, den0, num1, den1]
__device__ int g_done;

__device__ __forceinline__ float fsqrt_approx(float x) {
    float r; asm("sqrt.approx.f32 %0, %1;" : "=f"(r) : "f"(x)); return r;
}

// sum of 4 sigmoids sigma(t - x), t in {0.5,1,2,4}; rational: 1 exp + 1 div
__device__ __forceinline__ float sig4c(float x) {
    const float C0 = 0.60653066f, C1 = 0.36787944f, C2 = 0.13533528f, C3 = 0.018315639f;
    float e = __expf(x);
    float b0 = fmaf(e, C0, 1.0f), b1 = fmaf(e, C1, 1.0f);
    float b2 = fmaf(e, C2, 1.0f), b3 = fmaf(e, C3, 1.0f);
    float p01 = b0 * b1, p23 = b2 * b3;
    float numr = fmaf(b0 + b1, p23, (b2 + b3) * p01);
    return __fdividef(numr, p01 * p23);
}

__device__ __forceinline__ void accum_pair(
    float px, float py, float pz, float tx, float ty, float tz,
    float nuc675, float4 jp, float4 jt, const float2* __restrict__ tbl,
    float& num, float& den, bool active)
{
    float dx = px - jp.x, dy = py - jp.y, dz = pz - jp.z;
    float d2p = fmaf(dx, dx, fmaf(dy, dy, dz * dz));
    float ex = tx - jt.x, ey = ty - jt.y, ez = tz - jt.z;
    float d2t = fmaf(ex, ex, fmaf(ey, ey, ez * ez));

    float cut2 = fmaf(jp.w, nuc675, 225.0f);            // 225 or 900
    float m = (d2t < cut2 && active) ? jt.w : 0.0f;     // cm_i folded out

    float dd = fminf(fabsf(fsqrt_approx(d2t) - fsqrt_approx(d2p)), DD_CLAMP);
    float t = dd * TBL_SCALE;
    int k = (int)t;
    float frac = t - (float)k;
    float2 e = tbl[k];
    float v = fmaf(frac, e.y, e.x);                     // = 4 * eps

    num = fmaf(v, m, num);
    den += m;
}

__global__ void __launch_bounds__(128)
lddt_fused(const float* __restrict__ pred,
           const float* __restrict__ truec,
           const int* __restrict__ is_dna,
           const int* __restrict__ is_rna,
           const int* __restrict__ cmask,
           float* __restrict__ out)
{
    // decode (batch, I, Jh): row I has 64 - 4I valid 64-wide j-tiles (Jh >= 4I)
    int lin = blockIdx.x;
    const int b = (lin >= NTILES_B) ? 1 : 0;
    lin -= b * NTILES_B;
    int I = 0;
    {
        int cnt = 64;
        while (lin >= cnt) { lin -= cnt; I++; cnt -= 4; }
    }
    const int Jh = 4 * I + lin;
    const bool hot = (lin >= 4);       // tile fully above the diagonal

    const int tid = threadIdx.x;

    __shared__ float2 tbl[TBL_N];
    __shared__ float tail;             // sig4 value at x = 16
    __shared__ float4 sjp[TJ];         // pred xyz, w = nuc flag
    __shared__ float4 sjt[TJ];         // true xyz, w = coords_mask(j)

    // pass 1: one sig4c per node (values into .x)
    for (int k = tid; k < TBL_N; k += 128)
        tbl[k].x = sig4c((float)k * TBL_H);
    if (tid == 0) tail = sig4c(16.0f);

    const int base = b * NTOK;

    // stage j-tile (threads 0..63)
    if (tid < TJ) {
        const int jg = base + Jh * TJ + tid;
        float4 p, t;
        p.x = pred[3 * jg + 0]; p.y = pred[3 * jg + 1]; p.z = pred[3 * jg + 2];
        t.x = truec[3 * jg + 0]; t.y = truec[3 * jg + 1]; t.z = truec[3 * jg + 2];
        p.w = (is_dna[jg] != 0 || is_rna[jg] != 0) ? 1.0f : 0.0f;
        t.w = (cmask[jg] != 0) ? 1.0f : 0.0f;
        sjp[tid] = p;
        sjt[tid] = t;
    }
    __syncthreads();

    // pass 2: slopes from neighbors
    for (int k = tid; k < TBL_N; k += 128) {
        float v1 = (k + 1 < TBL_N) ? tbl[k + 1].x : tail;
        tbl[k].y = v1 - tbl[k].x;
    }

    // own rows
    const int ig0 = base + I * TI + tid;
    const int ig1 = ig0 + 128;
    const float p0x = pred[3 * ig0 + 0], p0y = pred[3 * ig0 + 1], p0z = pred[3 * ig0 + 2];
    const float t0x = truec[3 * ig0 + 0], t0y = truec[3 * ig0 + 1], t0z = truec[3 * ig0 + 2];
    const float p1x = pred[3 * ig1 + 0], p1y = pred[3 * ig1 + 1], p1z = pred[3 * ig1 + 2];
    const float t1x = truec[3 * ig1 + 0], t1y = truec[3 * ig1 + 1], t1z = truec[3 * ig1 + 2];
    const float nuc0 = (is_dna[ig0] != 0 || is_rna[ig0] != 0) ? 675.0f : 0.0f;
    const float nuc1 = (is_dna[ig1] != 0 || is_rna[ig1] != 0) ? 675.0f : 0.0f;
    const float cm0 = (cmask[ig0] != 0) ? 1.0f : 0.0f;
    const float cm1 = (cmask[ig1] != 0) ? 1.0f : 0.0f;

    __syncthreads();

    float n0 = 0.0f, d0 = 0.0f, n1 = 0.0f, d1 = 0.0f;

    if (hot) {
        // branch-free: every column is strictly above both rows
        #pragma unroll 4
        for (int j = 0; j < TJ; ++j) {
            float4 jp = sjp[j];
            float4 jt = sjt[j];
            accum_pair(p0x, p0y, p0z, t0x, t0y, t0z, nuc0, jp, jt, tbl, n0, d0, true);
            accum_pair(p1x, p1y, p1z, t1x, t1y, t1z, nuc1, jp, jt, tbl, n1, d1, true);
        }
    } else {
        // diagonal-straddling tile: predicate on jcol > irow
        const int i0 = I * TI + tid;
        const int i1 = i0 + 128;
        const int jbase = Jh * TJ;
        #pragma unroll 2
        for (int j = 0; j < TJ; ++j) {
            float4 jp = sjp[j];
            float4 jt = sjt[j];
            const int jcol = jbase + j;
            accum_pair(p0x, p0y, p0z, t0x, t0y, t0z, nuc0, jp, jt, tbl, n0, d0, jcol > i0);
            accum_pair(p1x, p1y, p1z, t1x, t1y, t1z, nuc1, jp, jt, tbl, n1, d1, jcol > i1);
        }
    }

    float acc_num = fmaf(n0, cm0, n1 * cm1);
    float acc_den = fmaf(d0, cm0, d1 * cm1);

    #pragma unroll
    for (int o = 16; o > 0; o >>= 1) {
        acc_num += __shfl_xor_sync(0xFFFFFFFFu, acc_num, o);
        acc_den += __shfl_xor_sync(0xFFFFFFFFu, acc_den, o);
    }
    __shared__ float rn[4], rd[4];
    const int wid = tid >> 5;
    if ((tid & 31) == 0) { rn[wid] = acc_num; rd[wid] = acc_den; }
    __syncthreads();

    if (tid == 0) {
        float tn = rn[0] + rn[1] + rn[2] + rn[3];
        float td = rd[0] + rd[1] + rd[2] + rd[3];
        atomicAdd(&g_acc[2 * b + 0], (double)tn);
        atomicAdd(&g_acc[2 * b + 1], (double)td);
        __threadfence();
        int done = atomicAdd(&g_done, 1);
        if (done == TOTAL_CTAS - 1) {
            volatile double* acc = g_acc;
            double num0 = acc[0], den0 = acc[1], num1 = acc[2], den1 = acc[3];
            double e0 = 2.0 * den0; if (e0 < 1.0) e0 = 1.0;
            double e1 = 2.0 * den1; if (e1 < 1.0) e1 = 1.0;
            double l0 = (0.5 * num0) / e0;   // 2 * 0.25 * num / (2*den)
            double l1 = (0.5 * num1) / e1;
            out[0] = (float)(1.0 - 0.5 * (l0 + l1));
            acc[0] = 0.0; acc[1] = 0.0; acc[2] = 0.0; acc[3] = 0.0;
            g_done = 0;
            __threadfence();
        }
    }
}

extern "C" void kernel_launch(void* const* d_in, const int* in_sizes, int n_in,
                              void* d_out, int out_size) {
    const float* pred  = (const float*)d_in[0];
    const float* truec = (const float*)d_in[1];
    const int*   dna   = (const int*)d_in[2];
    const int*   rna   = (const int*)d_in[3];
    const int*   cm    = (const int*)d_in[4];

    lddt_fused<<<TOTAL_CTAS, 128>>>(pred, truec, dna, rna, cm, (float*)d_out);
}

// round 6
// speedup vs baseline: 1.2184x; 1.0703x over previous
#include <cuda_runtime.h>
#include <cuda_bf16.h>

// SmoothLDDTLoss — b=2, n=4096. Single fused kernel.
// Upper-triangle, 256x32 tiles (IR=2 rows/thread), 2176 CTAs (~59 warps/SM).
// Interpolated smem LUT (512 bins) for the 4-sigmoid sum; cheap 2-pass fill.

#define NTOK 4096
#define TJ 32
#define TI 256
#define NTILES_B 1088             // sum_{I=0}^{15} (128 - 8I)
#define TOTAL_CTAS (2 * NTILES_B)

#define TBL_N 512
#define TBL_H 0.03125f            // 16 / 512
#define TBL_SCALE 32.0f
#define DD_CLAMP 15.96875f        // 511 * H

__device__ double g_acc[4];       // [num0, den0, num1, den1]
__device__ int g_done;

__device__ __forceinline__ float fsqrt_approx(float x) {
    float r; asm("sqrt.approx.f32 %0, %1;" : "=f"(r) : "f"(x)); return r;
}

// sum of 4 sigmoids sigma(t - x), t in {0.5,1,2,4}; rational: 1 exp + 1 div
__device__ __forceinline__ float sig4c(float x) {
    const float C0 = 0.60653066f, C1 = 0.36787944f, C2 = 0.13533528f, C3 = 0.018315639f;
    float e = __expf(x);
    float b0 = fmaf(e, C0, 1.0f), b1 = fmaf(e, C1, 1.0f);
    float b2 = fmaf(e, C2, 1.0f), b3 = fmaf(e, C3, 1.0f);
    float p01 = b0 * b1, p23 = b2 * b3;
    float numr = fmaf(b0 + b1, p23, (b2 + b3) * p01);
    return __fdividef(numr, p01 * p23);
}

__device__ __forceinline__ void accum_pair(
    float px, float py, float pz, float tx, float ty, float tz,
    float nuc675, float4 jp, float4 jt, const float2* __restrict__ tbl,
    float& num, float& den, bool active)
{
    float dx = px - jp.x, dy = py - jp.y, dz = pz - jp.z;
    float d2p = fmaf(dx, dx, fmaf(dy, dy, dz * dz));
    float ex = tx - jt.x, ey = ty - jt.y, ez = tz - jt.z;
    float d2t = fmaf(ex, ex, fmaf(ey, ey, ez * ez));

    float cut2 = fmaf(jp.w, nuc675, 225.0f);            // 225 or 900
    float m = (d2t < cut2 && active) ? jt.w : 0.0f;     // cm_i folded out

    float dd = fminf(fabsf(fsqrt_approx(d2t) - fsqrt_approx(d2p)), DD_CLAMP);
    float t = dd * TBL_SCALE;
    int k = (int)t;
    float frac = t - (float)k;
    float2 e = tbl[k];
    float v = fmaf(frac, e.y, e.x);                     // = 4 * eps

    num = fmaf(v, m, num);
    den += m;
}

__global__ void __launch_bounds__(128)
lddt_fused(const float* __restrict__ pred,
           const float* __restrict__ truec,
           const int* __restrict__ is_dna,
           const int* __restrict__ is_rna,
           const int* __restrict__ cmask,
           float* __restrict__ out)
{
    // decode (batch, I, Jh): row I (16 rows of 256) has 128 - 8I valid
    // 32-wide j-tiles, Jh = 8I + lin
    int lin = blockIdx.x;
    const int b = (lin >= NTILES_B) ? 1 : 0;
    lin -= b * NTILES_B;
    int I = 0;
    {
        int cnt = 128;
        while (lin >= cnt) { lin -= cnt; I++; cnt -= 8; }
    }
    const int Jh = 8 * I + lin;
    const bool hot = (lin >= 8);       // tile fully above the diagonal

    const int tid = threadIdx.x;

    __shared__ float2 tbl[TBL_N];
    __shared__ float tail;             // sig4 value at x = 16
    __shared__ float4 sjp[TJ];         // pred xyz, w = nuc flag
    __shared__ float4 sjt[TJ];         // true xyz, w = coords_mask(j)

    // pass 1: one sig4c per node (values into .x)
    for (int k = tid; k < TBL_N; k += 128)
        tbl[k].x = sig4c((float)k * TBL_H);
    if (tid == 0) tail = sig4c(16.0f);

    const int base = b * NTOK;

    // stage j-tile (threads 0..31)
    if (tid < TJ) {
        const int jg = base + Jh * TJ + tid;
        float4 p, t;
        p.x = pred[3 * jg + 0]; p.y = pred[3 * jg + 1]; p.z = pred[3 * jg + 2];
        t.x = truec[3 * jg + 0]; t.y = truec[3 * jg + 1]; t.z = truec[3 * jg + 2];
        p.w = (is_dna[jg] != 0 || is_rna[jg] != 0) ? 1.0f : 0.0f;
        t.w = (cmask[jg] != 0) ? 1.0f : 0.0f;
        sjp[tid] = p;
        sjt[tid] = t;
    }
    __syncthreads();

    // pass 2: slopes from neighbors
    for (int k = tid; k < TBL_N; k += 128) {
        float v1 = (k + 1 < TBL_N) ? tbl[k + 1].x : tail;
        tbl[k].y = v1 - tbl[k].x;
    }

    // own rows
    const int ig0 = base + I * TI + tid;
    const int ig1 = ig0 + 128;
    const float p0x = pred[3 * ig0 + 0], p0y = pred[3 * ig0 + 1], p0z = pred[3 * ig0 + 2];
    const float t0x = truec[3 * ig0 + 0], t0y = truec[3 * ig0 + 1], t0z = truec[3 * ig0 + 2];
    const float p1x = pred[3 * ig1 + 0], p1y = pred[3 * ig1 + 1], p1z = pred[3 * ig1 + 2];
    const float t1x = truec[3 * ig1 + 0], t1y = truec[3 * ig1 + 1], t1z = truec[3 * ig1 + 2];
    const float nuc0 = (is_dna[ig0] != 0 || is_rna[ig0] != 0) ? 675.0f : 0.0f;
    const float nuc1 = (is_dna[ig1] != 0 || is_rna[ig1] != 0) ? 675.0f : 0.0f;
    const float cm0 = (cmask[ig0] != 0) ? 1.0f : 0.0f;
    const float cm1 = (cmask[ig1] != 0) ? 1.0f : 0.0f;

    __syncthreads();

    float n0 = 0.0f, d0 = 0.0f, n1 = 0.0f, d1 = 0.0f;

    if (hot) {
        // branch-free: every column is strictly above both rows
        #pragma unroll 8
        for (int j = 0; j < TJ; ++j) {
            float4 jp = sjp[j];
            float4 jt = sjt[j];
            accum_pair(p0x, p0y, p0z, t0x, t0y, t0z, nuc0, jp, jt, tbl, n0, d0, true);
            accum_pair(p1x, p1y, p1z, t1x, t1y, t1z, nuc1, jp, jt, tbl, n1, d1, true);
        }
    } else {
        // diagonal-straddling tile: predicate on jcol > irow
        const int i0 = I * TI + tid;
        const int i1 = i0 + 128;
        const int jbase = Jh * TJ;
        #pragma unroll 4
        for (int j = 0; j < TJ; ++j) {
            float4 jp = sjp[j];
            float4 jt = sjt[j];
            const int jcol = jbase + j;
            accum_pair(p0x, p0y, p0z, t0x, t0y, t0z, nuc0, jp, jt, tbl, n0, d0, jcol > i0);
            accum_pair(p1x, p1y, p1z, t1x, t1y, t1z, nuc1, jp, jt, tbl, n1, d1, jcol > i1);
        }
    }

    float acc_num = fmaf(n0, cm0, n1 * cm1);
    float acc_den = fmaf(d0, cm0, d1 * cm1);

    #pragma unroll
    for (int o = 16; o > 0; o >>= 1) {
        acc_num += __shfl_xor_sync(0xFFFFFFFFu, acc_num, o);
        acc_den += __shfl_xor_sync(0xFFFFFFFFu, acc_den, o);
    }
    __shared__ float rn[4], rd[4];
    const int wid = tid >> 5;
    if ((tid & 31) == 0) { rn[wid] = acc_num; rd[wid] = acc_den; }
    __syncthreads();

    if (tid == 0) {
        float tn = rn[0] + rn[1] + rn[2] + rn[3];
        float td = rd[0] + rd[1] + rd[2] + rd[3];
        atomicAdd(&g_acc[2 * b + 0], (double)tn);
        atomicAdd(&g_acc[2 * b + 1], (double)td);
        __threadfence();
        int done = atomicAdd(&g_done, 1);
        if (done == TOTAL_CTAS - 1) {
            volatile double* acc = g_acc;
            double num0 = acc[0], den0 = acc[1], num1 = acc[2], den1 = acc[3];
            double e0 = 2.0 * den0; if (e0 < 1.0) e0 = 1.0;
            double e1 = 2.0 * den1; if (e1 < 1.0) e1 = 1.0;
            double l0 = (0.5 * num0) / e0;   // 2 * 0.25 * num / (2*den)
            double l1 = (0.5 * num1) / e1;
            out[0] = (float)(1.0 - 0.5 * (l0 + l1));
            acc[0] = 0.0; acc[1] = 0.0; acc[2] = 0.0; acc[3] = 0.0;
            g_done = 0;
            __threadfence();
        }
    }
}

extern "C" void kernel_launch(void* const* d_in, const int* in_sizes, int n_in,
                              void* d_out, int out_size) {
    const float* pred  = (const float*)d_in[0];
    const float* truec = (const float*)d_in[1];
    const int*   dna   = (const int*)d_in[2];
    const int*   rna   = (const int*)d_in[3];
    const int*   cm    = (const int*)d_in[4];

    lddt_fused<<<TOTAL_CTAS, 128>>>(pred, truec, dna, rna, cm, (float*)d_out);
}

// round 7
// speedup vs baseline: 1.2803x; 1.0507x over previous
#include <cuda_runtime.h>
#include <cuda_bf16.h>

// SmoothLDDTLoss — b=2, n=4096. Single fused kernel.
// Upper-triangle, 256x32 tiles (IR=2 rows/thread), 2176 CTAs.
// Dot-product distance form (3 FFMA + 1 FADD per d^2, matching reference numerics),
// coords_mask_j folded into the true-norm, magic-index LUT with pre-baked
// (base, slope) so eval is 1 FFMA + 1 FFMA + LDS.64.

#define NTOK 4096
#define TJ 32
#define TI 256
#define NTILES_B 1088             // sum_{I=0}^{15} (128 - 8I)
#define TOTAL_CTAS (2 * NTILES_B)

#define TBL_N 512
#define TBL_H 0.03125f            // 16 / 512
#define DD_CLAMP 15.96875f        // 511 * H
#define MASK_BIG 2097152.0f       // 2^21 >> max cutoff^2 (900)

__device__ double g_acc[4];       // [num0, den0, num1, den1]
__device__ int g_done;

__device__ __forceinline__ float fsqrt_approx(float x) {
    float r; asm("sqrt.approx.f32 %0, %1;" : "=f"(r) : "f"(x)); return r;
}

// sum of 4 sigmoids sigma(t - x), t in {0.5,1,2,4}; rational: 1 exp + 1 div
__device__ __forceinline__ float sig4c(float x) {
    const float C0 = 0.60653066f, C1 = 0.36787944f, C2 = 0.13533528f, C3 = 0.018315639f;
    float e = __expf(x);
    float b0 = fmaf(e, C0, 1.0f), b1 = fmaf(e, C1, 1.0f);
    float b2 = fmaf(e, C2, 1.0f), b3 = fmaf(e, C3, 1.0f);
    float p01 = b0 * b1, p23 = b2 * b3;
    float numr = fmaf(b0 + b1, p23, (b2 + b3) * p01);
    return __fdividef(numr, p01 * p23);
}

struct RowS {
    float ax, ay, az, sp;   // -2*pred_i, |pred_i|^2
    float bx, by, bz, st;   // -2*true_i, |true_i|^2
    float nuc;              // 1 if nucleotide else 0
};

// one pair, dot-product form. A=(px,py,pz,|p|^2), B=(tx,ty,tz,|t|^2+maskbig), cj=675*wp_j
__device__ __forceinline__ void pair_dot(
    const RowS& r, float4 A, float4 B, float cj,
    const float2* __restrict__ tbl, float& num, float& den, bool active)
{
    float d2p = fmaf(r.ax, A.x, fmaf(r.ay, A.y, fmaf(r.az, A.z, r.sp))) + A.w;
    float d2t = fmaf(r.bx, B.x, fmaf(r.by, B.y, fmaf(r.bz, B.z, r.st))) + B.w;

    float cut2 = fmaf(r.nuc, cj, 225.0f);               // 225 or 900
    float mm = (d2t < cut2 && active) ? 1.0f : 0.0f;

    float dd = fminf(fabsf(fsqrt_approx(d2t) - fsqrt_approx(d2p)), DD_CLAMP);
    int k = __float_as_int(fmaf(dd, 32.0f, 8388608.0f)) & 0x1FF;
    float2 e = tbl[k];
    float v = fmaf(dd, e.y, e.x);                       // = 4 * eps

    num = fmaf(v, mm, num);
    den += mm;
}

__global__ void __launch_bounds__(128)
lddt_fused(const float* __restrict__ pred,
           const float* __restrict__ truec,
           const int* __restrict__ is_dna,
           const int* __restrict__ is_rna,
           const int* __restrict__ cmask,
           float* __restrict__ out)
{
    // decode (batch, I, Jh): row I (16 rows of 256) has 128 - 8I j-tiles
    int lin = blockIdx.x;
    const int b = (lin >= NTILES_B) ? 1 : 0;
    lin -= b * NTILES_B;
    int I = 0;
    {
        int cnt = 128;
        while (lin >= cnt) { lin -= cnt; I++; cnt -= 8; }
    }
    const int Jh = 8 * I + lin;
    const bool hot = (lin >= 8);

    const int tid = threadIdx.x;

    __shared__ float2 tbl[TBL_N];      // (v_k - k*s_k, 32*s_k)
    __shared__ float vraw[TBL_N + 1];  // raw sig4 node values
    __shared__ float4 sA[TJ];          // pred xyz, |p|^2
    __shared__ float4 sB[TJ];          // true xyz, |t|^2 + (wt?0:BIG)
    __shared__ float  sC[TJ];          // 675 * wp_j

    for (int k = tid; k < TBL_N; k += 128)
        vraw[k] = sig4c((float)k * TBL_H);
    if (tid == 0) vraw[TBL_N] = sig4c(16.0f);

    const int base = b * NTOK;

    if (tid < TJ) {
        const int jg = base + Jh * TJ + tid;
        float px = pred[3 * jg + 0], py = pred[3 * jg + 1], pz = pred[3 * jg + 2];
        float tx = truec[3 * jg + 0], ty = truec[3 * jg + 1], tz = truec[3 * jg + 2];
        float np = fmaf(px, px, fmaf(py, py, pz * pz));
        float nt = fmaf(tx, tx, fmaf(ty, ty, tz * tz));
        bool wt = (cmask[jg] != 0);
        sA[tid] = make_float4(px, py, pz, np);
        sB[tid] = make_float4(tx, ty, tz, wt ? nt : nt + MASK_BIG);
        sC[tid] = (is_dna[jg] != 0 || is_rna[jg] != 0) ? 675.0f : 0.0f;
    }
    __syncthreads();

    // bake (base, slope*32) per bin
    for (int k = tid; k < TBL_N; k += 128) {
        float v0 = vraw[k];
        float s = vraw[k + 1] - v0;
        tbl[k] = make_float2(fmaf(-(float)k, s, v0), s * 32.0f);
    }

    // own rows
    const int ig0 = base + I * TI + tid;
    const int ig1 = ig0 + 128;
    RowS r0, r1;
    {
        float px = pred[3 * ig0 + 0], py = pred[3 * ig0 + 1], pz = pred[3 * ig0 + 2];
        float tx = truec[3 * ig0 + 0], ty = truec[3 * ig0 + 1], tz = truec[3 * ig0 + 2];
        r0.ax = -2.0f * px; r0.ay = -2.0f * py; r0.az = -2.0f * pz;
        r0.sp = fmaf(px, px, fmaf(py, py, pz * pz));
        r0.bx = -2.0f * tx; r0.by = -2.0f * ty; r0.bz = -2.0f * tz;
        r0.st = fmaf(tx, tx, fmaf(ty, ty, tz * tz));
        r0.nuc = (is_dna[ig0] != 0 || is_rna[ig0] != 0) ? 1.0f : 0.0f;
    }
    {
        float px = pred[3 * ig1 + 0], py = pred[3 * ig1 + 1], pz = pred[3 * ig1 + 2];
        float tx = truec[3 * ig1 + 0], ty = truec[3 * ig1 + 1], tz = truec[3 * ig1 + 2];
        r1.ax = -2.0f * px; r1.ay = -2.0f * py; r1.az = -2.0f * pz;
        r1.sp = fmaf(px, px, fmaf(py, py, pz * pz));
        r1.bx = -2.0f * tx; r1.by = -2.0f * ty; r1.bz = -2.0f * tz;
        r1.st = fmaf(tx, tx, fmaf(ty, ty, tz * tz));
        r1.nuc = (is_dna[ig1] != 0 || is_rna[ig1] != 0) ? 1.0f : 0.0f;
    }
    const float cm0 = (cmask[ig0] != 0) ? 1.0f : 0.0f;
    const float cm1 = (cmask[ig1] != 0) ? 1.0f : 0.0f;

    __syncthreads();

    float n0 = 0.0f, d0 = 0.0f, n1 = 0.0f, d1 = 0.0f;

    if (hot) {
        #pragma unroll 8
        for (int j = 0; j < TJ; ++j) {
            float4 A = sA[j];
            float4 B = sB[j];
            float cj = sC[j];
            pair_dot(r0, A, B, cj, tbl, n0, d0, true);
            pair_dot(r1, A, B, cj, tbl, n1, d1, true);
        }
    } else {
        const int i0 = I * TI + tid;
        const int i1 = i0 + 128;
        const int jbase = Jh * TJ;
        #pragma unroll 4
        for (int j = 0; j < TJ; ++j) {
            float4 A = sA[j];
            float4 B = sB[j];
            float cj = sC[j];
            const int jcol = jbase + j;
            pair_dot(r0, A, B, cj, tbl, n0, d0, jcol > i0);
            pair_dot(r1, A, B, cj, tbl, n1, d1, jcol > i1);
        }
    }

    float acc_num = fmaf(n0, cm0, n1 * cm1);
    float acc_den = fmaf(d0, cm0, d1 * cm1);

    #pragma unroll
    for (int o = 16; o > 0; o >>= 1) {
        acc_num += __shfl_xor_sync(0xFFFFFFFFu, acc_num, o);
        acc_den += __shfl_xor_sync(0xFFFFFFFFu, acc_den, o);
    }
    __shared__ float rn[4], rd[4];
    const int wid = tid >> 5;
    if ((tid & 31) == 0) { rn[wid] = acc_num; rd[wid] = acc_den; }
    __syncthreads();

    if (tid == 0) {
        float tn = rn[0] + rn[1] + rn[2] + rn[3];
        float td = rd[0] + rd[1] + rd[2] + rd[3];
        atomicAdd(&g_acc[2 * b + 0], (double)tn);
        atomicAdd(&g_acc[2 * b + 1], (double)td);
        __threadfence();
        int done = atomicAdd(&g_done, 1);
        if (done == TOTAL_CTAS - 1) {
            volatile double* acc = g_acc;
            double num0 = acc[0], den0 = acc[1], num1 = acc[2], den1 = acc[3];
            double e0 = 2.0 * den0; if (e0 < 1.0) e0 = 1.0;
            double e1 = 2.0 * den1; if (e1 < 1.0) e1 = 1.0;
            double l0 = (0.5 * num0) / e0;   // 2 * 0.25 * num / (2*den)
            double l1 = (0.5 * num1) / e1;
            out[0] = (float)(1.0 - 0.5 * (l0 + l1));
            acc[0] = 0.0; acc[1] = 0.0; acc[2] = 0.0; acc[3] = 0.0;
            g_done = 0;
            __threadfence();
        }
    }
}

extern "C" void kernel_launch(void* const* d_in, const int* in_sizes, int n_in,
                              void* d_out, int out_size) {
    const float* pred  = (const float*)d_in[0];
    const float* truec = (const float*)d_in[1];
    const int*   dna   = (const int*)d_in[2];
    const int*   rna   = (const int*)d_in[3];
    const int*   cm    = (const int*)d_in[4];

    lddt_fused<<<TOTAL_CTAS, 128>>>(pred, truec, dna, rna, cm, (float*)d_out);
}